// round 12
// baseline (speedup 1.0000x reference)
#include <cuda_runtime.h>
#include <cstdint>

// ActorNetwork_mid_concat: 7 sequential tiny-MLP evaluations with argmax-driven
// state updates. Single cluster of 8 CTAs x 512 threads; w3 (128x2048) split
// into 8 register-resident 128x256 slices. Cross-CTA partial exchange via
// DSMEM (mapa + st.shared::cluster) with one barrier.cluster per step.
// No global scratch, no L2 flag polling -> graph-replay safe by construction.
// R12 fix: w4s prologue load was range-broken at 512 threads (left 384..767
// uninitialized) -> restored strided loop.

#define NCTA  8
#define NTHR  512
#define NSTEP 7

__device__ __forceinline__ uint32_t smem_u32(const void* p) {
    return (uint32_t)__cvta_generic_to_shared(p);
}
__device__ __forceinline__ void st_cluster_f32(uint32_t local_addr, uint32_t rank, float v) {
    uint32_t rem;
    asm volatile("mapa.shared::cluster.u32 %0, %1, %2;" : "=r"(rem) : "r"(local_addr), "r"(rank));
    asm volatile("st.shared::cluster.f32 [%0], %1;" :: "r"(rem), "f"(v) : "memory");
}
__device__ __forceinline__ void cluster_arrive_wait() {
    asm volatile("barrier.cluster.arrive.aligned;" ::: "memory");
    asm volatile("barrier.cluster.wait.aligned;" ::: "memory");
}
__device__ __forceinline__ uint32_t ctarank() {
    uint32_t r; asm("mov.u32 %0, %%cluster_ctarank;" : "=r"(r)); return r;
}

__global__ __launch_bounds__(NTHR, 1) __cluster_dims__(NCTA, 1, 1)
void actor_net_kernel(const float* __restrict__ inp,
                      const float* __restrict__ conv_w, const float* __restrict__ conv_b,
                      const float* __restrict__ w0, const float* __restrict__ b0,
                      const float* __restrict__ w1, const float* __restrict__ b1,
                      const float* __restrict__ w2, const float* __restrict__ b2,
                      const float* __restrict__ w3, const float* __restrict__ b3,
                      const float* __restrict__ w4, const float* __restrict__ b4,
                      float* __restrict__ out)
{
    __shared__ __align__(16) float featb[256];            // this CTA's feat slice
    __shared__ __align__(16) float part[2][NCTA][128];    // double-buffered partials (DSMEM target)
    __shared__ float cw[128 * 4], cb[128];
    __shared__ float w0s[128], b0s[128], w1s[128], b1s[128], w2s[128], b2s[128];
    __shared__ float b3s[128];
    __shared__ float w4s[6 * 128], b4s[6];
    __shared__ float st[6][8], bw[8], vcs[6];
    __shared__ float hbuf[128], lg[6];

    const int tid  = threadIdx.x;
    const uint32_t rank = ctarank();

    // ---- Prologue: small weights + state into SMEM (all CTAs load everything) ----
    for (int i = tid; i < 512; i += NTHR) cw[i] = conv_w[i];
    if (tid < 128) {
        cb[tid]  = conv_b[tid];
        w0s[tid] = w0[tid];  b0s[tid] = b0[tid];
        w1s[tid] = w1[tid];  b1s[tid] = b1[tid];
        w2s[tid] = w2[tid];  b2s[tid] = b2[tid];
        b3s[tid] = b3[tid];
    }
    for (int i = tid; i < 768; i += NTHR) w4s[i] = w4[i];
    if (tid < 6)  b4s[tid] = b4[tid];
    if (tid < 48) st[tid >> 3][tid & 7] = inp[tid];
    if (tid >= 48 && tid < 56) bw[tid - 48] = inp[tid];
    if (tid < 6)  vcs[tid] = inp[56] * (float)(1 << tid);   // vs * {1,2,4,8,16,32}

    // ---- w3 slice -> registers: thread t holds row r = t>>2, quarter q = t&3 ----
    // CTA covers cols [rank*256, rank*256+256); thread covers 64 of them.
    const int r = tid >> 2;
    const int q = tid & 3;
    float4 W[16];
    const float4* w3row =
        reinterpret_cast<const float4*>(w3 + (size_t)r * 2048 + rank * 256 + q * 64);
#pragma unroll
    for (int i = 0; i < 16; i++) W[i] = __ldg(&w3row[i]);

    __syncthreads();

    for (int s = 0; s < NSTEP; ++s) {
        // ---- Phase A: build only this CTA's 256 feat values ----
        if (tid < 256) {
            const int j = (int)rank * 256 + tid;   // global feat index
            float val;
            if (j < 128) {
                val = fmaxf(fmaf(st[0][7], w0s[j], b0s[j]), 0.0f);            // s0
            } else if (j < 256) {
                const int f = j - 128;
                val = fmaxf(fmaf(st[1][7], w1s[f], b1s[f]), 0.0f);            // s1
            } else if (j < 1920) {
                int row, f, k;
                if (j < 896)       { const int jj = j - 256;  row = 2; f = jj / 5; k = jj - f * 5; }
                else if (j < 1536) { const int jj = j - 896;  row = 3; f = jj / 5; k = jj - f * 5; }
                else               { const int jj = j - 1536; row = 4; f = jj / 3; k = jj - f * 3; }
                float v = cb[f];
                v = fmaf(st[row][k],     cw[f * 4 + 0], v);
                v = fmaf(st[row][k + 1], cw[f * 4 + 1], v);
                v = fmaf(st[row][k + 2], cw[f * 4 + 2], v);
                v = fmaf(st[row][k + 3], cw[f * 4 + 3], v);
                val = fmaxf(v, 0.0f);
            } else {
                const int f = j - 1920;
                val = fmaf(st[4][7], w2s[f], b2s[f]);                         // s5: no relu
            }
            featb[tid] = val;
        }
        __syncthreads();

        // ---- Phase B: register-resident partial matvec (this CTA's 256 cols) ----
        const float4* fp = reinterpret_cast<const float4*>(featb + q * 64);
        float4 acc = make_float4(0.f, 0.f, 0.f, 0.f);
#pragma unroll
        for (int i = 0; i < 16; i++) {
            const float4 f4 = fp[i];
            acc.x = fmaf(W[i].x, f4.x, acc.x);
            acc.y = fmaf(W[i].y, f4.y, acc.y);
            acc.z = fmaf(W[i].z, f4.z, acc.z);
            acc.w = fmaf(W[i].w, f4.w, acc.w);
        }
        float p = (acc.x + acc.y) + (acc.z + acc.w);
        p += __shfl_xor_sync(0xffffffffu, p, 1);   // butterfly: all 4 lanes of row r
        p += __shfl_xor_sync(0xffffffffu, p, 2);   // end with the full row partial

        // ---- Phase C: push partial to every CTA's SMEM (incl. own), 2 ranks/thread ----
        const int buf = s & 1;
        {
            const uint32_t dst = smem_u32(&part[buf][rank][r]);
            st_cluster_f32(dst, (uint32_t)(2 * q),     p);
            st_cluster_f32(dst, (uint32_t)(2 * q + 1), p);
        }
        // One cluster barrier per step: releases our DSMEM stores, acquires peers'.
        // Double buffering makes the next step's writes (buf^1) safe; step s+2's
        // reuse of buf is fenced by the barrier at step s+1.
        cluster_arrive_wait();

        // ---- Phase D: deterministic local reduce -> h (identical in every CTA) ----
        if (tid < 128) {
            float a = b3s[tid];
#pragma unroll
            for (int b = 0; b < NCTA; b++) a += part[buf][b][tid];
            hbuf[tid] = fmaxf(a, 0.0f);
        }
        __syncthreads();

        // ---- Phase E: logits = w4 @ h + b4 (6 warps) ----
        if (tid < 192) {
            const int a = tid >> 5, l = tid & 31;
            float v = 0.0f;
            v = fmaf(w4s[a * 128 + l],      hbuf[l],      v);
            v = fmaf(w4s[a * 128 + l + 32], hbuf[l + 32], v);
            v = fmaf(w4s[a * 128 + l + 64], hbuf[l + 64], v);
            v = fmaf(w4s[a * 128 + l + 96], hbuf[l + 96], v);
#pragma unroll
            for (int o = 16; o > 0; o >>= 1) v += __shfl_down_sync(0xffffffffu, v, o);
            if (l == 0) lg[a] = v + b4s[a];
        }
        __syncthreads();

        // ---- Phase F: argmax + state update (exact reference arithmetic) ----
        if (s < 6) {
            if (tid == 0) {
                int   a    = 0;
                float best = lg[0];
#pragma unroll
                for (int j = 1; j < 6; j++) if (lg[j] > best) { best = lg[j]; a = j; }
                const float vca   = vcs[a];
                const float delay = vca / bw[s] - 30000.0f;          // BUF
#pragma unroll
                for (int rr = 0; rr < 6; rr++) {                     // roll(-1, axis=1)
                    const float t0 = st[rr][0];
#pragma unroll
                    for (int j = 0; j < 7; j++) st[rr][j] = st[rr][j + 1];
                    st[rr][7] = t0;
                }
                const float VBR[6] = {300.f, 750.f, 1200.f, 1850.f, 2850.f, 4300.f};
                st[0][7] = VBR[a] / 4300.0f;
                st[1][7] = 3.0f;                                     // BUF/1000/10
                st[2][7] = vca / delay / 1000.0f;
                st[3][7] = delay / 1000.0f / 10.0f;
#pragma unroll
                for (int j = 0; j < 6; j++) st[4][j] = vcs[j] / 1000000.0f;
                st[5][7] = (7.0f - (float)s) / 8.0f;
            }
            __syncthreads();
        } else {
            if (rank == 0 && tid < 6) out[tid] = lg[tid];
        }
    }
}

extern "C" void kernel_launch(void* const* d_in, const int* in_sizes, int n_in,
                              void* d_out, int out_size)
{
    (void)in_sizes; (void)n_in; (void)out_size;
    actor_net_kernel<<<NCTA, NTHR>>>(
        (const float*)d_in[0],  (const float*)d_in[1],  (const float*)d_in[2],
        (const float*)d_in[3],  (const float*)d_in[4],  (const float*)d_in[5],
        (const float*)d_in[6],  (const float*)d_in[7],  (const float*)d_in[8],
        (const float*)d_in[9],  (const float*)d_in[10], (const float*)d_in[11],
        (const float*)d_in[12], (float*)d_out);
}